// round 3
// baseline (speedup 1.0000x reference)
#include <cuda_runtime.h>
#include <cstdint>
#include <cfloat>

// Problem constants
#define NN 65536
#define DD 128
#define MM 8
#define KK 256

// Tiling
#define BM      128          // rows per block
#define THREADS 512          // 16 warps; warp w handles rows w*8..w*8+7
#define CT_STRIDE 257        // 256 + 1 pad: conflict-free transpose stores & column reads
#define RT_STRIDE 132        // 128 + 4 pad: keeps float4 alignment, odd-ish banking for prep

// Shared memory layout (in floats)
#define SM_CT   0
#define SM_RT   (128 * CT_STRIDE)                  // 32896
#define SM_RSS  (SM_RT + 128 * RT_STRIDE)          // + 16896
#define SM_CSQ  (SM_RSS + 128)
#define SM_FLOATS (SM_CSQ + 256)                   // 50176 floats = 200704 bytes
#define SM_BYTES (SM_FLOATS * 4)

// One residual-quantization stage:
//   res = x - prev_recon           (prev_recon = side[stage-1], or 0 for stage 0)
//   d2[k] = (||res||^2 - 2*res.C_k) + ||C_k||^2 ; idx = argmin_k (first min)
//   recon = prev + C[idx]  -> side[stage]  (and x_recon if last stage)
//   codes[n, stage, :] = one-hot(idx)      (zeros written here too; no memset)
__global__ __launch_bounds__(THREADS, 1)
void rq_stage_kernel(const float* __restrict__ x,
                     const float* __restrict__ C,      // this stage's (K, D) codebook
                     float* __restrict__ codes,        // (N, M, K)
                     float* __restrict__ side,         // (M, N, D)
                     float* __restrict__ xrecon,       // (N, D)
                     int stage)
{
    extern __shared__ float sm[];
    float* Ct   = sm + SM_CT;    // Ct[d*CT_STRIDE + k]
    float* resT = sm + SM_RT;    // resT[d*RT_STRIDE + r]
    float* rss  = sm + SM_RSS;   // per-row ||res||^2
    float* csq  = sm + SM_CSQ;   // per-codeword ||c||^2

    const int tid     = threadIdx.x;
    const int rowBase = blockIdx.x * BM;

    const float* prev = (stage == 0) ? nullptr
                                     : (side + (size_t)(stage - 1) * NN * DD);

    // ---- Load codebook, transposed into smem (coalesced global, conflict-free smem) ----
    #pragma unroll
    for (int j = 0; j < (KK * DD) / THREADS; ++j) {
        int idx = tid + j * THREADS;
        float v = C[idx];
        int k = idx >> 7;        // idx / 128
        int d = idx & 127;
        Ct[d * CT_STRIDE + k] = v;
    }

    // ---- Compute residual tile, transposed into smem; accumulate per-row ||res||^2 ----
    {
        int r  = tid >> 2;              // 0..127 local row
        int c0 = (tid & 3) * 32;        // 32-col chunk
        const float* xrow = x + (size_t)(rowBase + r) * DD + c0;
        const float* prow = prev ? prev + (size_t)(rowBase + r) * DD + c0 : nullptr;
        float part = 0.f;
        #pragma unroll
        for (int j = 0; j < 32; j += 4) {
            float4 xv = *(const float4*)(xrow + j);
            float4 pv = prow ? *(const float4*)(prow + j) : make_float4(0.f, 0.f, 0.f, 0.f);
            float r0 = xv.x - pv.x, r1 = xv.y - pv.y;
            float r2 = xv.z - pv.z, r3 = xv.w - pv.w;
            resT[(c0 + j + 0) * RT_STRIDE + r] = r0;
            resT[(c0 + j + 1) * RT_STRIDE + r] = r1;
            resT[(c0 + j + 2) * RT_STRIDE + r] = r2;
            resT[(c0 + j + 3) * RT_STRIDE + r] = r3;
            part = fmaf(r0, r0, part); part = fmaf(r1, r1, part);
            part = fmaf(r2, r2, part); part = fmaf(r3, r3, part);
        }
        // reduce the 4 chunk-partials (lanes grouped mod 4). Order vs JAX is
        // irrelevant: rss is a per-row common-mode shift of d2 (no argmin effect).
        part += __shfl_xor_sync(0xffffffffu, part, 1);
        part += __shfl_xor_sync(0xffffffffu, part, 2);
        if ((tid & 3) == 0) rss[r] = part;
    }
    __syncthreads();

    // ---- ||c_k||^2 from the transposed codebook (conflict-free column reads) ----
    if (tid < KK) {
        float s = 0.f;
        #pragma unroll 8
        for (int d = 0; d < DD; ++d) {
            float v = Ct[d * CT_STRIDE + tid];
            s = fmaf(v, v, s);
        }
        csq[tid] = s;
    }
    __syncthreads();

    // ---- Main GEMM: acc[r][c] = sum_d res[row][d] * C[col][d] ----
    const int w    = tid >> 5;    // warp id: rows w*8 .. w*8+7
    const int lane = tid & 31;    // cols lane + 32*c  (c = 0..7)

    float acc[8][8];
    #pragma unroll
    for (int a = 0; a < 8; ++a)
        #pragma unroll
        for (int b = 0; b < 8; ++b)
            acc[a][b] = 0.f;

    const float* rbase = resT + w * 8;
    #pragma unroll 2
    for (int d = 0; d < DD; ++d) {
        float4 a0 = *(const float4*)(rbase + d * RT_STRIDE);      // broadcast
        float4 a1 = *(const float4*)(rbase + d * RT_STRIDE + 4);
        float av[8] = {a0.x, a0.y, a0.z, a0.w, a1.x, a1.y, a1.z, a1.w};
        float bv[8];
        #pragma unroll
        for (int c = 0; c < 8; ++c)
            bv[c] = Ct[d * CT_STRIDE + lane + 32 * c];            // coalesced
        #pragma unroll
        for (int rr = 0; rr < 8; ++rr)
            #pragma unroll
            for (int c = 0; c < 8; ++c)
                acc[rr][c] = fmaf(av[rr], bv[c], acc[rr][c]);
    }

    // ---- Epilogue: argmin (replicating JAX's (rss - 2E) + csq rounding), recon, outputs ----
    const bool last = (stage == MM - 1);
    float* sstage = side + (size_t)stage * NN * DD;

    #pragma unroll
    for (int rr = 0; rr < 8; ++rr) {
        int lrow = w * 8 + rr;
        int n    = rowBase + lrow;
        float rv = rss[lrow];

        float best = FLT_MAX;
        int   bidx = 0x7fffffff;
        #pragma unroll
        for (int c = 0; c < 8; ++c) {
            int k = lane + 32 * c;
            float t1 = __fadd_rn(rv, __fmul_rn(-2.0f, acc[rr][c]));  // rss - 2*dot
            float d2 = __fadd_rn(t1, csq[k]);                        // + csq
            if (d2 < best) { best = d2; bidx = k; }   // ascending k: first-min kept
        }
        // warp-wide argmin, lowest index wins ties (matches jnp.argmin)
        #pragma unroll
        for (int off = 16; off > 0; off >>= 1) {
            float ob = __shfl_xor_sync(0xffffffffu, best, off);
            int   oi = __shfl_xor_sync(0xffffffffu, bidx, off);
            if (ob < best || (ob == best && oi < bidx)) { best = ob; bidx = oi; }
        }

        // one-hot row (zeros + the 1.0), coalesced; replaces a 536MB serial memset
        float* crow_codes = codes + (size_t)n * (MM * KK) + (size_t)stage * KK;
        #pragma unroll
        for (int c = 0; c < 8; ++c) {
            int k = lane + 32 * c;
            crow_codes[k] = (k == bidx) ? 1.0f : 0.0f;
        }

        // recon row: prev + C[bidx], bit-exact vs reference recurrence
        const float* prow = prev ? prev + (size_t)n * DD : nullptr;
        float* srow = sstage + (size_t)n * DD;
        float* orow = xrecon + (size_t)n * DD;
        #pragma unroll
        for (int j = 0; j < 4; ++j) {
            int d = lane + 32 * j;
            float cv = Ct[d * CT_STRIDE + bidx];   // conflict-free (stride 257)
            float p  = prow ? prow[d] : 0.f;
            float v  = __fadd_rn(p, cv);
            srow[d] = v;
            if (last) orow[d] = v;
        }
    }
}

extern "C" void kernel_launch(void* const* d_in, const int* in_sizes, int n_in,
                              void* d_out, int out_size)
{
    (void)in_sizes; (void)n_in; (void)out_size;
    const float* x  = (const float*)d_in[0];            // (N, D)
    const float* cb = (const float*)d_in[1];            // (M, K, D)

    float* out    = (float*)d_out;
    float* xrecon = out;                                // (N, D)
    float* codes  = out + (size_t)NN * DD;              // (N, M, K)
    float* side   = codes + (size_t)NN * MM * KK;       // (M, N, D)

    cudaFuncSetAttribute(rq_stage_kernel,
                         cudaFuncAttributeMaxDynamicSharedMemorySize, SM_BYTES);

    const int grid = NN / BM;   // 512
    for (int i = 0; i < MM; ++i) {
        rq_stage_kernel<<<grid, THREADS, SM_BYTES>>>(
            x, cb + (size_t)i * KK * DD, codes, side, xrecon, i);
    }
}

// round 4
// speedup vs baseline: 1.1333x; 1.1333x over previous
#include <cuda_runtime.h>
#include <cstdint>
#include <cfloat>

// Problem constants
#define NN 65536
#define DD 128
#define MM 8
#define KK 256

// Tiling
#define BM      128          // rows per block
#define THREADS 512          // 16 warps; warp w handles rows w*8..w*8+7
#define CT_STRIDE 257        // 256 + 1 pad: conflict-free transpose stores & column reads
#define RT_STRIDE 132        // 128 + 4 pad: float4-aligned, even => b64 row-pair loads aligned

// Shared memory layout (in floats)
#define SM_CT   0
#define SM_RT   (128 * CT_STRIDE)                  // 32896
#define SM_RSS  (SM_RT + 128 * RT_STRIDE)          // + 16896
#define SM_CSQ  (SM_RSS + 128)
#define SM_FLOATS (SM_CSQ + 256)                   // 50176 floats = 200704 bytes
#define SM_BYTES (SM_FLOATS * 4)

// ---- packed f32x2 helpers (SASS FFMA2 path; per-half numerics identical to fmaf) ----
__device__ __forceinline__ unsigned long long pack2_dup(float v) {
    unsigned long long r;
    asm("mov.b64 %0, {%1, %1};" : "=l"(r) : "f"(v));
    return r;
}
__device__ __forceinline__ void fma2(unsigned long long& d,
                                     unsigned long long a, unsigned long long b) {
    asm("fma.rn.f32x2 %0, %1, %2, %0;" : "+l"(d) : "l"(a), "l"(b));
}
__device__ __forceinline__ void unpack2(float& lo, float& hi, unsigned long long v) {
    asm("mov.b64 {%0, %1}, %2;" : "=f"(lo), "=f"(hi) : "l"(v));
}

// One residual-quantization stage:
//   res = x - prev_recon           (prev_recon = side[stage-1], or 0 for stage 0)
//   d2[k] = (||res||^2 - 2*res.C_k) + ||C_k||^2 ; idx = argmin_k (first min)
//   recon = prev + C[idx]  -> side[stage]  (and x_recon if last stage)
//   codes[n, stage, :] = one-hot(idx)      (zeros written here too; no memset)
__global__ __launch_bounds__(THREADS, 1)
void rq_stage_kernel(const float* __restrict__ x,
                     const float* __restrict__ C,      // this stage's (K, D) codebook
                     float* __restrict__ codes,        // (N, M, K)
                     float* __restrict__ side,         // (M, N, D)
                     float* __restrict__ xrecon,       // (N, D)
                     int stage)
{
    extern __shared__ float sm[];
    float* Ct   = sm + SM_CT;    // Ct[d*CT_STRIDE + k]
    float* resT = sm + SM_RT;    // resT[d*RT_STRIDE + r]
    float* rss  = sm + SM_RSS;   // per-row ||res||^2
    float* csq  = sm + SM_CSQ;   // per-codeword ||c||^2

    const int tid     = threadIdx.x;
    const int rowBase = blockIdx.x * BM;

    const float* prev = (stage == 0) ? nullptr
                                     : (side + (size_t)(stage - 1) * NN * DD);

    // ---- Load codebook, transposed into smem (coalesced global, conflict-free smem) ----
    #pragma unroll
    for (int j = 0; j < (KK * DD) / THREADS; ++j) {
        int idx = tid + j * THREADS;
        float v = C[idx];
        int k = idx >> 7;        // idx / 128
        int d = idx & 127;
        Ct[d * CT_STRIDE + k] = v;
    }

    // ---- Compute residual tile, transposed into smem; accumulate per-row ||res||^2 ----
    {
        int r  = tid >> 2;              // 0..127 local row
        int c0 = (tid & 3) * 32;        // 32-col chunk
        const float* xrow = x + (size_t)(rowBase + r) * DD + c0;
        const float* prow = prev ? prev + (size_t)(rowBase + r) * DD + c0 : nullptr;
        float part = 0.f;
        #pragma unroll
        for (int j = 0; j < 32; j += 4) {
            float4 xv = *(const float4*)(xrow + j);
            float4 pv = prow ? *(const float4*)(prow + j) : make_float4(0.f, 0.f, 0.f, 0.f);
            float r0 = xv.x - pv.x, r1 = xv.y - pv.y;
            float r2 = xv.z - pv.z, r3 = xv.w - pv.w;
            resT[(c0 + j + 0) * RT_STRIDE + r] = r0;
            resT[(c0 + j + 1) * RT_STRIDE + r] = r1;
            resT[(c0 + j + 2) * RT_STRIDE + r] = r2;
            resT[(c0 + j + 3) * RT_STRIDE + r] = r3;
            part = fmaf(r0, r0, part); part = fmaf(r1, r1, part);
            part = fmaf(r2, r2, part); part = fmaf(r3, r3, part);
        }
        // reduce the 4 chunk-partials. Order vs JAX is irrelevant: rss is a
        // per-row common-mode shift of d2 (no argmin effect).
        part += __shfl_xor_sync(0xffffffffu, part, 1);
        part += __shfl_xor_sync(0xffffffffu, part, 2);
        if ((tid & 3) == 0) rss[r] = part;
    }
    __syncthreads();

    // ---- ||c_k||^2 from the transposed codebook (conflict-free column reads) ----
    if (tid < KK) {
        float s = 0.f;
        #pragma unroll 8
        for (int d = 0; d < DD; ++d) {
            float v = Ct[d * CT_STRIDE + tid];
            s = fmaf(v, v, s);
        }
        csq[tid] = s;
    }
    __syncthreads();

    // ---- Main GEMM via packed FFMA2: acc[r][c] = sum_d res[row][d] * C[col][d] ----
    // Accumulator halves pair consecutive ROWS: acc2[p][c] = {row 2p, row 2p+1}.
    // 'a' pair = two consecutive floats in resT -> one aligned ld.shared.b64
    // (broadcast); 'b' (k = lane + 32*c) duplicated into both halves.
    const int w    = tid >> 5;    // warp id: rows w*8 .. w*8+7
    const int lane = tid & 31;    // cols lane + 32*c  (c = 0..7)

    unsigned long long acc2[4][8];
    #pragma unroll
    for (int p = 0; p < 4; ++p)
        #pragma unroll
        for (int c = 0; c < 8; ++c)
            acc2[p][c] = 0ull;

    const float* rbase = resT + w * 8;
    #pragma unroll 4
    for (int d = 0; d < DD; ++d) {
        unsigned long long av2[4];
        #pragma unroll
        for (int p = 0; p < 4; ++p)
            av2[p] = *(const unsigned long long*)(rbase + d * RT_STRIDE + 2 * p);
        unsigned long long bv2[8];
        #pragma unroll
        for (int c = 0; c < 8; ++c)
            bv2[c] = pack2_dup(Ct[d * CT_STRIDE + lane + 32 * c]);   // coalesced LDS.32
        #pragma unroll
        for (int p = 0; p < 4; ++p)
            #pragma unroll
            for (int c = 0; c < 8; ++c)
                fma2(acc2[p][c], av2[p], bv2[c]);
    }

    // ---- Epilogue: argmin (replicating JAX's (rss - 2E) + csq rounding), recon, outputs ----
    const bool last = (stage == MM - 1);
    float* sstage = side + (size_t)stage * NN * DD;

    #pragma unroll
    for (int rr = 0; rr < 8; ++rr) {
        // extract this row's 8 dot products from the packed accumulators
        float accr[8];
        #pragma unroll
        for (int c = 0; c < 8; ++c) {
            float lo, hi;
            unpack2(lo, hi, acc2[rr >> 1][c]);
            accr[c] = (rr & 1) ? hi : lo;
        }

        int lrow = w * 8 + rr;
        int n    = rowBase + lrow;
        float rv = rss[lrow];

        float best = FLT_MAX;
        int   bidx = 0x7fffffff;
        #pragma unroll
        for (int c = 0; c < 8; ++c) {
            int k = lane + 32 * c;
            float t1 = __fadd_rn(rv, __fmul_rn(-2.0f, accr[c]));     // rss - 2*dot
            float d2 = __fadd_rn(t1, csq[k]);                        // + csq
            if (d2 < best) { best = d2; bidx = k; }   // ascending k: first-min kept
        }
        // warp-wide argmin, lowest index wins ties (matches jnp.argmin)
        #pragma unroll
        for (int off = 16; off > 0; off >>= 1) {
            float ob = __shfl_xor_sync(0xffffffffu, best, off);
            int   oi = __shfl_xor_sync(0xffffffffu, bidx, off);
            if (ob < best || (ob == best && oi < bidx)) { best = ob; bidx = oi; }
        }

        // one-hot row (zeros + the 1.0), coalesced; replaces a 536MB serial memset
        float* crow_codes = codes + (size_t)n * (MM * KK) + (size_t)stage * KK;
        #pragma unroll
        for (int c = 0; c < 8; ++c) {
            int k = lane + 32 * c;
            crow_codes[k] = (k == bidx) ? 1.0f : 0.0f;
        }

        // recon row: prev + C[bidx], bit-exact vs reference recurrence
        const float* prow = prev ? prev + (size_t)n * DD : nullptr;
        float* srow = sstage + (size_t)n * DD;
        float* orow = xrecon + (size_t)n * DD;
        #pragma unroll
        for (int j = 0; j < 4; ++j) {
            int d = lane + 32 * j;
            float cv = Ct[d * CT_STRIDE + bidx];   // conflict-free (stride 257)
            float p  = prow ? prow[d] : 0.f;
            float v  = __fadd_rn(p, cv);
            srow[d] = v;
            if (last) orow[d] = v;
        }
    }
}

extern "C" void kernel_launch(void* const* d_in, const int* in_sizes, int n_in,
                              void* d_out, int out_size)
{
    (void)in_sizes; (void)n_in; (void)out_size;
    const float* x  = (const float*)d_in[0];            // (N, D)
    const float* cb = (const float*)d_in[1];            // (M, K, D)

    float* out    = (float*)d_out;
    float* xrecon = out;                                // (N, D)
    float* codes  = out + (size_t)NN * DD;              // (N, M, K)
    float* side   = codes + (size_t)NN * MM * KK;       // (M, N, D)

    cudaFuncSetAttribute(rq_stage_kernel,
                         cudaFuncAttributeMaxDynamicSharedMemorySize, SM_BYTES);

    const int grid = NN / BM;   // 512
    for (int i = 0; i < MM; ++i) {
        rq_stage_kernel<<<grid, THREADS, SM_BYTES>>>(
            x, cb + (size_t)i * KK * DD, codes, side, xrecon, i);
    }
}